// round 2
// baseline (speedup 1.0000x reference)
#include <cuda_runtime.h>
#include <math.h>

#define THREADS 512
#define NWARP 16

// Shared memory layout (in floats):
//  [0,16384)      W1 row-major copy      (backward: W1[j][k], k consecutive)
//  [16384,32768)  W1 transposed          (forward:  W1T[k][j], j consecutive)
//  [32768,35200)  W0 transposed [19][128]
//  [35200,35328)  b0
//  [35328,35456)  b1
//  [35456,35584)  Wo
//  [35584,35600)  bo (+pad)
//  [35600, +16*320) per-warp staging: a0[128] | d1[128] | h[32] | gh[32]
#define SMEM_FLOATS (35600 + NWARP * 320)

__device__ __forceinline__ float shx(float v, int m) {
    return __shfl_xor_sync(0xFFFFFFFFu, v, m);
}

__global__ void __launch_bounds__(THREADS, 1)
neural_sdf_kernel(const float* __restrict__ pos,
                  const float* __restrict__ grid,
                  const float* __restrict__ W0g,
                  const float* __restrict__ b0g,
                  const float* __restrict__ W1g,
                  const float* __restrict__ b1g,
                  const float* __restrict__ Wog,
                  const float* __restrict__ bog,
                  float* __restrict__ out,
                  int n_pts)
{
    extern __shared__ float sm[];
    float* W1row = sm;               // 16384
    float* W1T   = sm + 16384;       // 16384
    float* W0T   = sm + 32768;       // 19*128
    float* b0s   = sm + 35200;
    float* b1s   = sm + 35328;
    float* Wos   = sm + 35456;
    float* bos   = sm + 35584;
    float* stag  = sm + 35600;

    const int tid = threadIdx.x;

    // ---- cooperative weight preload ----
    for (int idx = tid; idx < 128 * 128; idx += THREADS) {
        float v = W1g[idx];
        W1row[idx] = v;
        int j = idx >> 7, k = idx & 127;
        W1T[(k << 7) + j] = v;
    }
    for (int idx = tid; idx < 128 * 19; idx += THREADS) {
        int j = idx / 19;
        int i = idx - j * 19;
        W0T[(i << 7) + j] = W0g[idx];   // W0T[i][j] = W0[j][i]
    }
    if (tid < 128) {
        b0s[tid] = b0g[tid];
        b1s[tid] = b1g[tid];
        Wos[tid] = Wog[tid];
    }
    if (tid == 0) bos[0] = bog[0];
    __syncthreads();

    const int w    = tid >> 5;
    const int lane = tid & 31;
    float* a0s = stag + w * 320;
    float* d1s = a0s + 128;
    float* hs  = d1s + 128;   // 32 slots, first 19 used
    float* ghs = hs + 32;     // 32 slots, first 19 used

    const int e    = lane & 15;
    const int half = lane >> 4;
    const int j0   = lane << 2;          // this lane's 4 hidden units

    const int gw = blockIdx.x * NWARP + w;
    const int nw = gridDim.x * NWARP;

    for (int n = gw; n < n_pts; n += nw) {
        // ---- position transform & cell setup ----
        float px = fmaf(pos[3 * n + 0], 0.5f, 0.5f);
        float py = fmaf(pos[3 * n + 1], 0.5f, 0.5f);
        float pz = fmaf(pos[3 * n + 2], 0.5f, 0.5f);
        float xx = px * 127.0f, xy = py * 127.0f, xz = pz * 127.0f;
        int ix = min(126, max(0, (int)floorf(xx)));
        int iy = min(126, max(0, (int)floorf(xy)));
        int iz = min(126, max(0, (int)floorf(xz)));
        float fx = xx - (float)ix;
        float fy = xy - (float)iy;
        float fz = xz - (float)iz;
        int base = ((ix << 7) + iy) * 128 + iz;

        // ---- trilinear gather + spatial derivative (lanes split: channel e, 4 corners/half) ----
        float emb = 0.f, dex = 0.f, dey = 0.f, dez = 0.f;
        #pragma unroll
        for (int cc = 0; cc < 4; cc++) {
            int c  = (half << 2) + cc;
            int dx = (c >> 2) & 1, dy = (c >> 1) & 1, dz = c & 1;
            float wx = dx ? fx : 1.0f - fx;
            float wy = dy ? fy : 1.0f - fy;
            float wz = dz ? fz : 1.0f - fz;
            int gi = base + (dx << 14) + (dy << 7) + dz;
            float g = __ldg(grid + (gi << 4) + e);
            float wyz = wy * wz, wxz = wx * wz, wxy = wx * wy;
            emb = fmaf(g, wx * wyz, emb);
            float gyz = g * wyz, gxz = g * wxz, gxy = g * wxy;
            dex += dx ? gyz : -gyz;
            dey += dy ? gxz : -gxz;
            dez += dz ? gxy : -gxy;
        }
        emb += shx(emb, 16);
        dex += shx(dex, 16); dex *= 127.0f;
        dey += shx(dey, 16); dey *= 127.0f;
        dez += shx(dez, 16); dez *= 127.0f;

        if (lane < 16) hs[e] = emb;
        if (lane == 16) { hs[16] = px; hs[17] = py; hs[18] = pz; }
        __syncwarp();

        // ---- layer 0 forward: z0[j] = W0[j,:] . h + b0[j] ----
        float4 bb = *(const float4*)(b0s + j0);
        float z0[4] = {bb.x, bb.y, bb.z, bb.w};
        #pragma unroll
        for (int i = 0; i < 19; i++) {
            float hv = hs[i];
            float4 wv = *(const float4*)(W0T + (i << 7) + j0);
            z0[0] = fmaf(wv.x, hv, z0[0]);
            z0[1] = fmaf(wv.y, hv, z0[1]);
            z0[2] = fmaf(wv.z, hv, z0[2]);
            z0[3] = fmaf(wv.w, hv, z0[3]);
        }
        float s0[4], c0[4];
        #pragma unroll
        for (int u = 0; u < 4; u++) __sincosf(30.0f * z0[u], &s0[u], &c0[u]);
        *(float4*)(a0s + j0) = make_float4(s0[0], s0[1], s0[2], s0[3]);
        __syncwarp();

        // ---- layer 1 forward: z1[j] = W1[j,:] . a0 + b1[j] ----
        bb = *(const float4*)(b1s + j0);
        float z1[4] = {bb.x, bb.y, bb.z, bb.w};
        #pragma unroll 8
        for (int k = 0; k < 128; k++) {
            float av = a0s[k];
            float4 wv = *(const float4*)(W1T + (k << 7) + j0);
            z1[0] = fmaf(wv.x, av, z1[0]);
            z1[1] = fmaf(wv.y, av, z1[1]);
            z1[2] = fmaf(wv.z, av, z1[2]);
            z1[3] = fmaf(wv.w, av, z1[3]);
        }
        float s1[4], c1[4];
        #pragma unroll
        for (int u = 0; u < 4; u++) __sincosf(30.0f * z1[u], &s1[u], &c1[u]);

        // ---- output head + sdf reduce ----
        float4 wo = *(const float4*)(Wos + j0);
        float sp = wo.x * s1[0] + wo.y * s1[1] + wo.z * s1[2] + wo.w * s1[3];
        #pragma unroll
        for (int m = 16; m; m >>= 1) sp += shx(sp, m);
        float sdf = sp + bos[0];

        // ---- backward: d1[j] = Wo[j] * 30 cos(30 z1[j]) ----
        float d1a0 = wo.x * 30.0f * c1[0];
        float d1a1 = wo.y * 30.0f * c1[1];
        float d1a2 = wo.z * 30.0f * c1[2];
        float d1a3 = wo.w * 30.0f * c1[3];
        *(float4*)(d1s + j0) = make_float4(d1a0, d1a1, d1a2, d1a3);
        __syncwarp();

        // ---- backward through W1: g0[k] = sum_j W1[j][k] d1[j] ----
        float g0[4] = {0.f, 0.f, 0.f, 0.f};
        #pragma unroll 8
        for (int j = 0; j < 128; j++) {
            float dv = d1s[j];
            float4 wv = *(const float4*)(W1row + (j << 7) + j0);
            g0[0] = fmaf(wv.x, dv, g0[0]);
            g0[1] = fmaf(wv.y, dv, g0[1]);
            g0[2] = fmaf(wv.z, dv, g0[2]);
            g0[3] = fmaf(wv.w, dv, g0[3]);
        }
        float d0[4];
        #pragma unroll
        for (int u = 0; u < 4; u++) d0[u] = g0[u] * 30.0f * c0[u];

        // ---- backward through W0: gh[i] = sum_j W0[j][i] d0[j] ----
        float gh[19];
        #pragma unroll
        for (int i = 0; i < 19; i++) {
            float4 wv = *(const float4*)(W0T + (i << 7) + j0);
            gh[i] = wv.x * d0[0] + wv.y * d0[1] + wv.z * d0[2] + wv.w * d0[3];
        }
        #pragma unroll
        for (int i = 0; i < 19; i++) {
            #pragma unroll
            for (int m = 16; m; m >>= 1) gh[i] += shx(gh[i], m);
        }
        if (lane == 0) {
            #pragma unroll
            for (int i = 0; i < 19; i++) ghs[i] = gh[i];
        }
        __syncwarp();

        // ---- assemble spatial gradient ----
        float p0, p1, p2;
        if (lane < 16) {
            float ge = ghs[e];
            p0 = ge * dex; p1 = ge * dey; p2 = ge * dez;
        } else {
            p0 = 0.f; p1 = 0.f; p2 = 0.f;
        }
        #pragma unroll
        for (int m = 16; m; m >>= 1) {
            p0 += shx(p0, m);
            p1 += shx(p1, m);
            p2 += shx(p2, m);
        }
        if (lane == 0) {
            out[n] = sdf;
            float* go = out + n_pts + 3 * n;
            go[0] = p0 + ghs[16];
            go[1] = p1 + ghs[17];
            go[2] = p2 + ghs[18];
        }
        __syncwarp();   // protect staging buffers before next iteration
    }
}

extern "C" void kernel_launch(void* const* d_in, const int* in_sizes, int n_in,
                              void* d_out, int out_size) {
    const float* pos  = (const float*)d_in[0];
    const float* grid = (const float*)d_in[1];
    const float* W0   = (const float*)d_in[2];
    const float* b0   = (const float*)d_in[3];
    const float* W1   = (const float*)d_in[4];
    const float* b1   = (const float*)d_in[5];
    const float* Wo   = (const float*)d_in[6];
    const float* bo   = (const float*)d_in[7];
    int n_pts = in_sizes[0] / 3;

    size_t smem = (size_t)SMEM_FLOATS * sizeof(float);
    cudaFuncSetAttribute(neural_sdf_kernel,
                         cudaFuncAttributeMaxDynamicSharedMemorySize, (int)smem);
    neural_sdf_kernel<<<148, THREADS, smem>>>(pos, grid, W0, b0, W1, b1, Wo, bo,
                                              (float*)d_out, n_pts);
}

// round 3
// speedup vs baseline: 2.3569x; 2.3569x over previous
#include <cuda_runtime.h>
#include <math.h>

#define THREADS 384
#define NWARP 12
#define PB 8

// shared layout (floats)
#define OFF_W1ROW 0
#define OFF_W1T   16384
#define OFF_W0T   32768            // 20 rows x 128 (row 19 zeroed)
#define OFF_B0    35328
#define OFF_B1    35456
#define OFF_WO    35584
#define OFF_STAGE 35716
#define WARP_STAGE 1568            // buf 1024 | hs 160 | dEs 384
#define SMEM_FLOATS (OFF_STAGE + NWARP * WARP_STAGE)

__device__ __forceinline__ float shx(float v, int m) {
    return __shfl_xor_sync(0xFFFFFFFFu, v, m);
}

__global__ void __launch_bounds__(THREADS, 1)
neural_sdf_kernel(const float* __restrict__ pos,
                  const float* __restrict__ grid,
                  const float* __restrict__ W0g,
                  const float* __restrict__ b0g,
                  const float* __restrict__ W1g,
                  const float* __restrict__ b1g,
                  const float* __restrict__ Wog,
                  const float* __restrict__ bog,
                  float* __restrict__ out,
                  int n_pts)
{
    extern __shared__ float sm[];
    float* W1row = sm + OFF_W1ROW;
    float* W1T   = sm + OFF_W1T;
    float* W0T   = sm + OFF_W0T;
    float* b0s   = sm + OFF_B0;
    float* b1s   = sm + OFF_B1;
    float* Wos   = sm + OFF_WO;

    const int tid = threadIdx.x;

    // ---- cooperative weight preload ----
    for (int idx = tid; idx < 128 * 128; idx += THREADS) {
        float v = W1g[idx];
        W1row[idx] = v;
        int j = idx >> 7, k = idx & 127;
        W1T[(k << 7) + j] = v;
    }
    for (int idx = tid; idx < 128 * 19; idx += THREADS) {
        int j = idx / 19;
        int i = idx - j * 19;
        W0T[(i << 7) + j] = W0g[idx];
    }
    if (tid < 128) {
        W0T[19 * 128 + tid] = 0.0f;     // zero pad row (i=19)
        b0s[tid] = b0g[tid];
        b1s[tid] = b1g[tid];
        Wos[tid] = Wog[tid];
    }
    __syncthreads();

    const int w    = tid >> 5;
    const int lane = tid & 31;
    float* buf = sm + OFF_STAGE + w * WARP_STAGE;  // a0 then d1 [p][128]
    float* hs  = buf + 1024;                        // [p][20]
    float* dEs = hs + 160;                          // [p][48]: dx16|dy16|dz16

    const int e    = lane & 15;
    const int half = lane >> 4;
    const int j0   = lane << 2;

    // hoisted per-lane constants
    const float4 b0_4 = *(const float4*)(b0s + j0);
    const float4 b1_4 = *(const float4*)(b1s + j0);
    const float4 wo4  = *(const float4*)(Wos + j0);
    const float  bo_r = __ldg(bog);

    const int gw = blockIdx.x * NWARP + w;
    const int nw = gridDim.x * NWARP;

    for (int n0 = gw * PB; n0 < n_pts; n0 += nw * PB) {

        // ================= gather: 8 points =================
        #pragma unroll
        for (int p = 0; p < PB; p++) {
            int n = n0 + p;
            int nc = (n < n_pts) ? n : (n_pts - 1);
            float px = fmaf(__ldg(pos + 3 * nc + 0), 0.5f, 0.5f);
            float py = fmaf(__ldg(pos + 3 * nc + 1), 0.5f, 0.5f);
            float pz = fmaf(__ldg(pos + 3 * nc + 2), 0.5f, 0.5f);
            float xx = px * 127.0f, xy = py * 127.0f, xz = pz * 127.0f;
            int ix = min(126, max(0, (int)floorf(xx)));
            int iy = min(126, max(0, (int)floorf(xy)));
            int iz = min(126, max(0, (int)floorf(xz)));
            float fx = xx - (float)ix;
            float fy = xy - (float)iy;
            float fz = xz - (float)iz;
            int base = ((ix << 7) + iy) * 128 + iz;

            float emb = 0.f, dex = 0.f, dey = 0.f, dez = 0.f;
            #pragma unroll
            for (int cc = 0; cc < 4; cc++) {
                int c  = (half << 2) + cc;
                int dx = (c >> 2) & 1, dy = (c >> 1) & 1, dz = c & 1;
                float wx = dx ? fx : 1.0f - fx;
                float wy = dy ? fy : 1.0f - fy;
                float wz = dz ? fz : 1.0f - fz;
                int gi = base + (dx << 14) + (dy << 7) + dz;
                float g = __ldg(grid + (gi << 4) + e);
                float wyz = wy * wz, wxz = wx * wz, wxy = wx * wy;
                emb = fmaf(g, wx * wyz, emb);
                float gyz = g * wyz, gxz = g * wxz, gxy = g * wxy;
                dex += dx ? gyz : -gyz;
                dey += dy ? gxz : -gxz;
                dez += dz ? gxy : -gxy;
            }
            emb += shx(emb, 16);
            dex += shx(dex, 16);
            dey += shx(dey, 16);
            dez += shx(dez, 16);

            if (lane < 16) {
                hs[p * 20 + e]       = emb;
                dEs[p * 48 + e]      = dex * 127.0f;
                dEs[p * 48 + 16 + e] = dey * 127.0f;
                dEs[p * 48 + 32 + e] = dez * 127.0f;
            } else if (lane == 16) {
                *(float4*)(hs + p * 20 + 16) = make_float4(px, py, pz, 0.0f);
            }
        }
        __syncwarp();

        // ================= layer 0 forward =================
        float z0[PB][4];
        #pragma unroll
        for (int p = 0; p < PB; p++) {
            z0[p][0] = b0_4.x; z0[p][1] = b0_4.y;
            z0[p][2] = b0_4.z; z0[p][3] = b0_4.w;
        }
        #pragma unroll
        for (int c = 0; c < 5; c++) {
            const float* wp = W0T + c * 512 + j0;
            float4 w0 = *(const float4*)(wp);
            float4 w1 = *(const float4*)(wp + 128);
            float4 w2 = *(const float4*)(wp + 256);
            float4 w3 = *(const float4*)(wp + 384);
            #pragma unroll
            for (int p = 0; p < PB; p++) {
                float4 h4 = *(const float4*)(hs + p * 20 + 4 * c);
                z0[p][0] = fmaf(w0.x,h4.x, fmaf(w1.x,h4.y, fmaf(w2.x,h4.z, fmaf(w3.x,h4.w, z0[p][0]))));
                z0[p][1] = fmaf(w0.y,h4.x, fmaf(w1.y,h4.y, fmaf(w2.y,h4.z, fmaf(w3.y,h4.w, z0[p][1]))));
                z0[p][2] = fmaf(w0.z,h4.x, fmaf(w1.z,h4.y, fmaf(w2.z,h4.z, fmaf(w3.z,h4.w, z0[p][2]))));
                z0[p][3] = fmaf(w0.w,h4.x, fmaf(w1.w,h4.y, fmaf(w2.w,h4.z, fmaf(w3.w,h4.w, z0[p][3]))));
            }
        }
        float c0r[PB][4];
        #pragma unroll
        for (int p = 0; p < PB; p++) {
            float4 s;
            __sincosf(30.0f * z0[p][0], &s.x, &c0r[p][0]);
            __sincosf(30.0f * z0[p][1], &s.y, &c0r[p][1]);
            __sincosf(30.0f * z0[p][2], &s.z, &c0r[p][2]);
            __sincosf(30.0f * z0[p][3], &s.w, &c0r[p][3]);
            *(float4*)(buf + p * 128 + j0) = s;
        }
        __syncwarp();

        // ================= layer 1 forward =================
        float z1[PB][4];
        #pragma unroll
        for (int p = 0; p < PB; p++) {
            z1[p][0] = b1_4.x; z1[p][1] = b1_4.y;
            z1[p][2] = b1_4.z; z1[p][3] = b1_4.w;
        }
        #pragma unroll 2
        for (int kc = 0; kc < 32; kc++) {
            const float* wp = W1T + kc * 512 + j0;
            float4 w0 = *(const float4*)(wp);
            float4 w1 = *(const float4*)(wp + 128);
            float4 w2 = *(const float4*)(wp + 256);
            float4 w3 = *(const float4*)(wp + 384);
            #pragma unroll
            for (int p = 0; p < PB; p++) {
                float4 a4 = *(const float4*)(buf + p * 128 + kc * 4);
                z1[p][0] = fmaf(w0.x,a4.x, fmaf(w1.x,a4.y, fmaf(w2.x,a4.z, fmaf(w3.x,a4.w, z1[p][0]))));
                z1[p][1] = fmaf(w0.y,a4.x, fmaf(w1.y,a4.y, fmaf(w2.y,a4.z, fmaf(w3.y,a4.w, z1[p][1]))));
                z1[p][2] = fmaf(w0.z,a4.x, fmaf(w1.z,a4.y, fmaf(w2.z,a4.z, fmaf(w3.z,a4.w, z1[p][2]))));
                z1[p][3] = fmaf(w0.w,a4.x, fmaf(w1.w,a4.y, fmaf(w2.w,a4.z, fmaf(w3.w,a4.w, z1[p][3]))));
            }
        }
        __syncwarp();   // all a0 reads done before d1 overwrites buf

        // ================= head + d1 =================
        float sdf[PB];
        #pragma unroll
        for (int p = 0; p < PB; p++) {
            float s1[4], c1[4];
            __sincosf(30.0f * z1[p][0], &s1[0], &c1[0]);
            __sincosf(30.0f * z1[p][1], &s1[1], &c1[1]);
            __sincosf(30.0f * z1[p][2], &s1[2], &c1[2]);
            __sincosf(30.0f * z1[p][3], &s1[3], &c1[3]);
            float sp = wo4.x*s1[0] + wo4.y*s1[1] + wo4.z*s1[2] + wo4.w*s1[3];
            #pragma unroll
            for (int m = 16; m; m >>= 1) sp += shx(sp, m);
            sdf[p] = sp + bo_r;
            *(float4*)(buf + p * 128 + j0) =
                make_float4(wo4.x*30.0f*c1[0], wo4.y*30.0f*c1[1],
                            wo4.z*30.0f*c1[2], wo4.w*30.0f*c1[3]);
        }
        __syncwarp();

        // ================= backward through W1 =================
        float g0[PB][4];
        #pragma unroll
        for (int p = 0; p < PB; p++) {
            g0[p][0] = 0.f; g0[p][1] = 0.f; g0[p][2] = 0.f; g0[p][3] = 0.f;
        }
        #pragma unroll 2
        for (int jc = 0; jc < 32; jc++) {
            const float* wp = W1row + jc * 512 + j0;
            float4 w0 = *(const float4*)(wp);
            float4 w1 = *(const float4*)(wp + 128);
            float4 w2 = *(const float4*)(wp + 256);
            float4 w3 = *(const float4*)(wp + 384);
            #pragma unroll
            for (int p = 0; p < PB; p++) {
                float4 d4 = *(const float4*)(buf + p * 128 + jc * 4);
                g0[p][0] = fmaf(w0.x,d4.x, fmaf(w1.x,d4.y, fmaf(w2.x,d4.z, fmaf(w3.x,d4.w, g0[p][0]))));
                g0[p][1] = fmaf(w0.y,d4.x, fmaf(w1.y,d4.y, fmaf(w2.y,d4.z, fmaf(w3.y,d4.w, g0[p][1]))));
                g0[p][2] = fmaf(w0.z,d4.x, fmaf(w1.z,d4.y, fmaf(w2.z,d4.z, fmaf(w3.z,d4.w, g0[p][2]))));
                g0[p][3] = fmaf(w0.w,d4.x, fmaf(w1.w,d4.y, fmaf(w2.w,d4.z, fmaf(w3.w,d4.w, g0[p][3]))));
            }
        }
        // d0 = g0 * 30 * cos(30 z0)
        #pragma unroll
        for (int p = 0; p < PB; p++) {
            g0[p][0] *= 30.0f * c0r[p][0];
            g0[p][1] *= 30.0f * c0r[p][1];
            g0[p][2] *= 30.0f * c0r[p][2];
            g0[p][3] *= 30.0f * c0r[p][3];
        }

        // ===== backward through W0 fused with gradient dot =====
        float gx[PB], gy[PB], gz[PB];
        #pragma unroll
        for (int p = 0; p < PB; p++) { gx[p] = 0.f; gy[p] = 0.f; gz[p] = 0.f; }

        #pragma unroll
        for (int i = 0; i < 16; i++) {
            float4 w4 = *(const float4*)(W0T + i * 128 + j0);
            #pragma unroll
            for (int p = 0; p < PB; p++) {
                float t = w4.x*g0[p][0] + w4.y*g0[p][1] + w4.z*g0[p][2] + w4.w*g0[p][3];
                gx[p] = fmaf(t, dEs[p * 48 + i],      gx[p]);
                gy[p] = fmaf(t, dEs[p * 48 + 16 + i], gy[p]);
                gz[p] = fmaf(t, dEs[p * 48 + 32 + i], gz[p]);
            }
        }
        {   // direct position inputs i = 16,17,18
            float4 wx4 = *(const float4*)(W0T + 16 * 128 + j0);
            float4 wy4 = *(const float4*)(W0T + 17 * 128 + j0);
            float4 wz4 = *(const float4*)(W0T + 18 * 128 + j0);
            #pragma unroll
            for (int p = 0; p < PB; p++) {
                gx[p] += wx4.x*g0[p][0] + wx4.y*g0[p][1] + wx4.z*g0[p][2] + wx4.w*g0[p][3];
                gy[p] += wy4.x*g0[p][0] + wy4.y*g0[p][1] + wy4.z*g0[p][2] + wy4.w*g0[p][3];
                gz[p] += wz4.x*g0[p][0] + wz4.y*g0[p][1] + wz4.z*g0[p][2] + wz4.w*g0[p][3];
            }
        }
        #pragma unroll
        for (int p = 0; p < PB; p++) {
            #pragma unroll
            for (int m = 16; m; m >>= 1) {
                gx[p] += shx(gx[p], m);
                gy[p] += shx(gy[p], m);
                gz[p] += shx(gz[p], m);
            }
        }

        if (lane == 0) {
            #pragma unroll
            for (int p = 0; p < PB; p++) {
                int n = n0 + p;
                if (n < n_pts) {
                    out[n] = sdf[p];
                    float* go = out + n_pts + 3 * n;
                    go[0] = gx[p]; go[1] = gy[p]; go[2] = gz[p];
                }
            }
        }
        __syncwarp();   // staging reused next batch
    }
}

extern "C" void kernel_launch(void* const* d_in, const int* in_sizes, int n_in,
                              void* d_out, int out_size) {
    const float* pos  = (const float*)d_in[0];
    const float* grid = (const float*)d_in[1];
    const float* W0   = (const float*)d_in[2];
    const float* b0   = (const float*)d_in[3];
    const float* W1   = (const float*)d_in[4];
    const float* b1   = (const float*)d_in[5];
    const float* Wo   = (const float*)d_in[6];
    const float* bo   = (const float*)d_in[7];
    int n_pts = in_sizes[0] / 3;

    size_t smem = (size_t)SMEM_FLOATS * sizeof(float);
    cudaFuncSetAttribute(neural_sdf_kernel,
                         cudaFuncAttributeMaxDynamicSharedMemorySize, (int)smem);
    neural_sdf_kernel<<<148, THREADS, smem>>>(pos, grid, W0, b0, W1, b1, Wo, bo,
                                              (float*)d_out, n_pts);
}